// round 13
// baseline (speedup 1.0000x reference)
#include <cuda_runtime.h>
#include <cuda_bf16.h>
#include <math.h>

// Problem constants
#define SD 128      // STATE_DIM
#define NH 32       // HIDDEN
#define BATCH 512
#define ROWS 4      // batch rows per block
#define THREADS 512 // 16 warps, role-partitioned; grid=128 -> one block per SM

// FINAL (converged R4 structure; benched 6.624us twice — R4, R11).
//
// Math identity (verified R1-R12, rel_err ~9.6e-8):
//   Every node sees the same feature row and the GCN normalization sums to 1
//   exactly for this graph, so both convs are per-batch matvecs and the
//   feature-mean collapses conv2 to a 32-dot with row-means of W2:
//   out[b,n] = exp(log_amp[n,month]) *
//     softplus( sum_h relu(x[b]@W1 + emb*W1[128,:] + b1)[h] * mean_n W2[h,n] + mean(b2) )
//
// Warp roles (one __syncthreads total):
//   warps 0-3  : matvec; warp c = input chunk c for ALL 4 rows (W1 read once, not 4x)
//   warps 4-7  : W2 row-means (8 rows each, coalesced float4)
//   warps 8-11 : amp table (exp(log_amp[:,month])); t-dependency broken by
//                loading all 12 months and selecting in registers
//   warp  12   : b2 mean
//   warps 12-15: phase-1 finishers (b1 / W1 emb row / emb prefetched pre-barrier)
//
// Falsified alternatives: bar.arrive producer split (R5), forced 32-deep W1
// register batch (R5), 256-thr blocks @ 2 CTA/SM (R8), straggler-self-finish
// (R9), 384-thr merge (R7), b2-mean on amp warp (R12). Remaining wall time is
// graph-replay + launch/DVFS ramp, not kernel work.

__global__ __launch_bounds__(THREADS, 1) void gnm_kernel(
    const float* __restrict__ x,        // [512,128]
    const float* __restrict__ t,        // [1]
    const float* __restrict__ log_amp,  // [128,12]
    const float* __restrict__ W1,       // [129,32]
    const float* __restrict__ b1,       // [32]
    const float* __restrict__ W2,       // [32,128]
    const float* __restrict__ b2,       // [128]
    float* __restrict__ out)            // [512,128]
{
    __shared__ float  s_part[4 * ROWS * NH];   // [chunk][row][h]
    __shared__ float  s_w2m[NH];               // W2 row means
    __shared__ float  s_amp[SD];
    __shared__ float  s_b2m;
    __shared__ float4 s_xt[4][NH];             // [chunk][j] = (x_row0..x_row3)[j]

    const int tid  = threadIdx.x;
    const int lane = tid & 31;
    const int warp = tid >> 5;
    const int b0   = blockIdx.x * ROWS;

    const float tv = t[0];

    if (warp < 4) {
        // ---------------- matvec: warp c handles chunk c for 4 rows ----------------
        const int c = warp;
        const float xv0 = x[(b0 + 0) * SD + c * 32 + lane];
        const float xv1 = x[(b0 + 1) * SD + c * 32 + lane];
        const float xv2 = x[(b0 + 2) * SD + c * 32 + lane];
        const float xv3 = x[(b0 + 3) * SD + c * 32 + lane];
        s_xt[c][lane] = make_float4(xv0, xv1, xv2, xv3);   // conflict-free STS.128
        __syncwarp();

        const float* __restrict__ w1p = W1 + (c * 32) * NH + lane;
        float p0a = 0.f, p1a = 0.f, p2a = 0.f, p3a = 0.f;
        float p0b = 0.f, p1b = 0.f, p2b = 0.f, p3b = 0.f;
        #pragma unroll
        for (int j = 0; j < 32; j += 2) {
            const float  w0 = w1p[(j + 0) * NH];   // coalesced LDG, shared by 4 rows
            const float  w1 = w1p[(j + 1) * NH];
            const float4 xa = s_xt[c][j + 0];      // LDS.128 broadcast
            const float4 xb = s_xt[c][j + 1];
            p0a = fmaf(xa.x, w0, p0a); p1a = fmaf(xa.y, w0, p1a);
            p2a = fmaf(xa.z, w0, p2a); p3a = fmaf(xa.w, w0, p3a);
            p0b = fmaf(xb.x, w1, p0b); p1b = fmaf(xb.y, w1, p1b);
            p2b = fmaf(xb.z, w1, p2b); p3b = fmaf(xb.w, w1, p3b);
        }
        s_part[c * (ROWS * NH) + 0 * NH + lane] = p0a + p0b;
        s_part[c * (ROWS * NH) + 1 * NH + lane] = p1a + p1b;
        s_part[c * (ROWS * NH) + 2 * NH + lane] = p2a + p2b;
        s_part[c * (ROWS * NH) + 3 * NH + lane] = p3a + p3b;
    } else if (warp < 8) {
        // ---------------- W2 row means: warp g, rows g*8 .. g*8+7 ----------------
        const int g = warp - 4;
        #pragma unroll
        for (int i = 0; i < 8; i++) {
            const int   r = g * 8 + i;
            const float4 v = reinterpret_cast<const float4*>(W2 + r * SD)[lane];
            float s = (v.x + v.y) + (v.z + v.w);
            #pragma unroll
            for (int off = 16; off; off >>= 1)
                s += __shfl_xor_sync(0xffffffffu, s, off);
            if (lane == 0) s_w2m[r] = s * (1.0f / SD);
        }
    } else if (warp < 12) {
        // ---------------- amp table: thread n = tid-256 in 0..127 ----------------
        const int n = tid - 256;
        const float4* lar = reinterpret_cast<const float4*>(log_amp + n * 12);
        const float4 la0 = lar[0], la1 = lar[1], la2 = lar[2];
        const float tm = (tv >= 12.0f) ? (tv - 12.0f) : tv;   // t in [0,24)
        const int month = (int)tm;
        float la = la0.x;
        la = (month ==  1) ? la0.y : la;
        la = (month ==  2) ? la0.z : la;
        la = (month ==  3) ? la0.w : la;
        la = (month ==  4) ? la1.x : la;
        la = (month ==  5) ? la1.y : la;
        la = (month ==  6) ? la1.z : la;
        la = (month ==  7) ? la1.w : la;
        la = (month ==  8) ? la2.x : la;
        la = (month ==  9) ? la2.y : la;
        la = (month == 10) ? la2.z : la;
        la = (month == 11) ? la2.w : la;
        s_amp[n] = __expf(la);
    }

    // ---------------- phase-1 owners: prefetch before the barrier ----------------
    float b1v = 0.f, w1e = 0.f, emb = 0.f;
    if (warp >= 12) {
        b1v = b1[lane];
        w1e = W1[SD * NH + lane];
        emb = __sinf(0.5235987755982988f * tv);   // sin(2*pi*t/12)
        if (warp == 12) {
            const float4 bv = reinterpret_cast<const float4*>(b2)[lane];
            float s = (bv.x + bv.y) + (bv.z + bv.w);
            #pragma unroll
            for (int off = 16; off; off >>= 1)
                s += __shfl_xor_sync(0xffffffffu, s, off);
            if (lane == 0) s_b2m = s * (1.0f / SD);
        }
    }

    __syncthreads();

    // ---------------- phase 1: warps 12-15, warp 12+r finishes row r ----------------
    if (warp >= 12) {
        const int r = warp - 12;
        const float* p = s_part + r * NH + lane;
        float v = ((p[0] + p[ROWS * NH]) + (p[2 * ROWS * NH] + p[3 * ROWS * NH]));
        v += fmaf(emb, w1e, b1v);

        float rsum = fmaxf(v, 0.0f) * s_w2m[lane];
        #pragma unroll
        for (int off = 16; off; off >>= 1)
            rsum += __shfl_xor_sync(0xffffffffu, rsum, off);

        const float m  = rsum + s_b2m;
        const float sp = fmaxf(m, 0.0f) + log1pf(__expf(-fabsf(m)));  // stable softplus

        const float4 av = reinterpret_cast<const float4*>(s_amp)[lane];
        float4 o;
        o.x = av.x * sp; o.y = av.y * sp; o.z = av.z * sp; o.w = av.w * sp;
        reinterpret_cast<float4*>(out + (b0 + r) * SD)[lane] = o;
    }
}

extern "C" void kernel_launch(void* const* d_in, const int* in_sizes, int n_in,
                              void* d_out, int out_size)
{
    const float* x       = (const float*)d_in[0];
    const float* t       = (const float*)d_in[1];
    const float* log_amp = (const float*)d_in[2];
    const float* W1      = (const float*)d_in[3];
    const float* b1      = (const float*)d_in[4];
    const float* W2      = (const float*)d_in[5];
    const float* b2      = (const float*)d_in[6];
    float* out           = (float*)d_out;

    gnm_kernel<<<BATCH / ROWS, THREADS>>>(x, t, log_amp, W1, b1, W2, b2, out);
}

// round 14
// speedup vs baseline: 1.0435x; 1.0435x over previous
#include <cuda_runtime.h>
#include <cuda_bf16.h>
#include <math.h>

// Problem constants
#define SD 128      // STATE_DIM
#define NH 32       // HIDDEN
#define BATCH 512
#define ROWS 4      // batch rows per block
#define THREADS 512 // 16 warps; grid=128 -> one block per SM

// Math identity (verified R1-R13, rel_err ~9.6e-8):
//   out[b,n] = exp(log_amp[n,month]) *
//     softplus( sum_h relu(x[b]@W1 + emb*W1[128,:] + b1)[h] * mean_n W2[h,n] + mean(b2) )
//
// Balanced warp roles (one __syncthreads; flattens the 230-vs-25 instr skew of
// the R4 structure):
//   warps 0-7  : matvec; warp (c = w&3, rp = w>>2) handles chunk c for rows
//                {2rp, 2rp+1} (~135 instr each; W1 LDGs shared pairwise via L1)
//   warps 8-11 : amp table + W2 row-means (8 rows each) (~105 instr);
//                warp 11 also b2 mean
//   warps 12-15: phase-1 finishers (b1 / W1 emb row / emb prefetched pre-barrier)

__global__ __launch_bounds__(THREADS, 1) void gnm_kernel(
    const float* __restrict__ x,        // [512,128]
    const float* __restrict__ t,        // [1]
    const float* __restrict__ log_amp,  // [128,12]
    const float* __restrict__ W1,       // [129,32]
    const float* __restrict__ b1,       // [32]
    const float* __restrict__ W2,       // [32,128]
    const float* __restrict__ b2,       // [128]
    float* __restrict__ out)            // [512,128]
{
    __shared__ float  s_part[4 * ROWS * NH];   // [chunk][row][h]
    __shared__ float  s_w2m[NH];               // W2 row means
    __shared__ float  s_amp[SD];
    __shared__ float  s_b2m;
    __shared__ float2 s_xt[4][2][NH];          // [chunk][rowpair][j] = (x_r0, x_r1)[j]

    const int tid  = threadIdx.x;
    const int lane = tid & 31;
    const int warp = tid >> 5;
    const int b0   = blockIdx.x * ROWS;

    const float tv = t[0];

    if (warp < 8) {
        // ---------------- matvec: warp (c, rp) handles chunk c, rows 2rp..2rp+1 ----------------
        const int c  = warp & 3;
        const int rp = warp >> 2;
        const float xv0 = x[(b0 + 2 * rp + 0) * SD + c * 32 + lane];
        const float xv1 = x[(b0 + 2 * rp + 1) * SD + c * 32 + lane];
        s_xt[c][rp][lane] = make_float2(xv0, xv1);   // conflict-free STS.64
        __syncwarp();

        const float* __restrict__ w1p = W1 + (c * 32) * NH + lane;
        float p0a = 0.f, p1a = 0.f, p0b = 0.f, p1b = 0.f;
        #pragma unroll
        for (int j = 0; j < 32; j += 2) {
            const float  w0 = w1p[(j + 0) * NH];   // coalesced LDG (pairwise L1-shared)
            const float  w1 = w1p[(j + 1) * NH];
            const float2 xa = s_xt[c][rp][j + 0];  // LDS.64 broadcast
            const float2 xb = s_xt[c][rp][j + 1];
            p0a = fmaf(xa.x, w0, p0a); p1a = fmaf(xa.y, w0, p1a);
            p0b = fmaf(xb.x, w1, p0b); p1b = fmaf(xb.y, w1, p1b);
        }
        s_part[c * (ROWS * NH) + (2 * rp + 0) * NH + lane] = p0a + p0b;
        s_part[c * (ROWS * NH) + (2 * rp + 1) * NH + lane] = p1a + p1b;
    } else if (warp < 12) {
        // ---------------- amp table + W2 row means ----------------
        const int n = tid - 256;                    // 0..127
        const float4* lar = reinterpret_cast<const float4*>(log_amp + n * 12);
        const float4 la0 = lar[0], la1 = lar[1], la2 = lar[2];
        const float tm = (tv >= 12.0f) ? (tv - 12.0f) : tv;   // t in [0,24)
        const int month = (int)tm;
        float la = la0.x;
        la = (month ==  1) ? la0.y : la;
        la = (month ==  2) ? la0.z : la;
        la = (month ==  3) ? la0.w : la;
        la = (month ==  4) ? la1.x : la;
        la = (month ==  5) ? la1.y : la;
        la = (month ==  6) ? la1.z : la;
        la = (month ==  7) ? la1.w : la;
        la = (month ==  8) ? la2.x : la;
        la = (month ==  9) ? la2.y : la;
        la = (month == 10) ? la2.z : la;
        la = (month == 11) ? la2.w : la;
        s_amp[n] = __expf(la);

        // W2 row means: warp g = warp-8, rows g*8 .. g*8+7 (coalesced float4)
        const int g = warp - 8;
        #pragma unroll
        for (int i = 0; i < 8; i++) {
            const int   r = g * 8 + i;
            const float4 v = reinterpret_cast<const float4*>(W2 + r * SD)[lane];
            float s = (v.x + v.y) + (v.z + v.w);
            #pragma unroll
            for (int off = 16; off; off >>= 1)
                s += __shfl_xor_sync(0xffffffffu, s, off);
            if (lane == 0) s_w2m[r] = s * (1.0f / SD);
        }

        if (warp == 11) {
            const float4 bv = reinterpret_cast<const float4*>(b2)[lane];
            float s = (bv.x + bv.y) + (bv.z + bv.w);
            #pragma unroll
            for (int off = 16; off; off >>= 1)
                s += __shfl_xor_sync(0xffffffffu, s, off);
            if (lane == 0) s_b2m = s * (1.0f / SD);
        }
    }

    // ---------------- phase-1 owners: prefetch before the barrier ----------------
    float b1v = 0.f, w1e = 0.f, emb = 0.f;
    if (warp >= 12) {
        b1v = b1[lane];
        w1e = W1[SD * NH + lane];
        emb = __sinf(0.5235987755982988f * tv);   // sin(2*pi*t/12)
    }

    __syncthreads();

    // ---------------- phase 1: warps 12-15, warp 12+r finishes row r ----------------
    if (warp >= 12) {
        const int r = warp - 12;
        const float* p = s_part + r * NH + lane;
        float v = ((p[0] + p[ROWS * NH]) + (p[2 * ROWS * NH] + p[3 * ROWS * NH]));
        v += fmaf(emb, w1e, b1v);

        float rsum = fmaxf(v, 0.0f) * s_w2m[lane];
        #pragma unroll
        for (int off = 16; off; off >>= 1)
            rsum += __shfl_xor_sync(0xffffffffu, rsum, off);

        const float m  = rsum + s_b2m;
        const float sp = fmaxf(m, 0.0f) + log1pf(__expf(-fabsf(m)));  // stable softplus

        const float4 av = reinterpret_cast<const float4*>(s_amp)[lane];
        float4 o;
        o.x = av.x * sp; o.y = av.y * sp; o.z = av.z * sp; o.w = av.w * sp;
        reinterpret_cast<float4*>(out + (b0 + r) * SD)[lane] = o;
    }
}

extern "C" void kernel_launch(void* const* d_in, const int* in_sizes, int n_in,
                              void* d_out, int out_size)
{
    const float* x       = (const float*)d_in[0];
    const float* t       = (const float*)d_in[1];
    const float* log_amp = (const float*)d_in[2];
    const float* W1      = (const float*)d_in[3];
    const float* b1      = (const float*)d_in[4];
    const float* W2      = (const float*)d_in[5];
    const float* b2      = (const float*)d_in[6];
    float* out           = (float*)d_out;

    gnm_kernel<<<BATCH / ROWS, THREADS>>>(x, t, log_amp, W1, b1, W2, b2, out);
}